// round 4
// baseline (speedup 1.0000x reference)
#include <cuda_runtime.h>

#define B 256
#define D 128
#define NEG 1024
#define SAMPLES 300000
#define TEMPR 0.07f
#define EPS 1e-12f

#define N4 ((SAMPLES * D) / 4)          // 9,600,000 float4 per memory array
#define NBLK 512                         // fused grid size
#define NWARP 16                         // warps per block
#define CSTRIDE (NBLK * NWARP * 32)      // 262144: copy stride in float4

__device__ __forceinline__ float warp_sum(float v) {
#pragma unroll
    for (int o = 16; o; o >>= 1) v += __shfl_down_sync(0xffffffffu, v, o);
    return v;
}

__device__ __forceinline__ float block_sum512(float v, volatile float* sm) {
    int lane = threadIdx.x & 31, w = threadIdx.x >> 5;
    float s = warp_sum(v);
    if (lane == 0) sm[w] = s;
    __syncthreads();
    float r = 0.f;
    if (threadIdx.x == 0) {
#pragma unroll
        for (int i = 0; i < 16; i++) r += sm[i];
        sm[16] = r;
    }
    __syncthreads();
    r = sm[16];
    __syncthreads();
    return r;
}

__device__ __forceinline__ float block_sum128(float v, volatile float* sm) {
    int lane = threadIdx.x & 31, w = threadIdx.x >> 5;
    float s = warp_sum(v);
    if (lane == 0) sm[w] = s;
    __syncthreads();
    float r = sm[0] + sm[1] + sm[2] + sm[3];
    __syncthreads();
    return r;
}

// int64 vs int32 detection (JAX x64 demotion hedge)
__device__ __forceinline__ bool is_i64(const void* p) {
    const int* q = (const int*)p;
    return ((q[1] | q[3] | q[5] | q[7]) == 0);
}
__device__ __forceinline__ long long ld_idx(const void* p, long long i, bool is64) {
    return is64 ? ((const long long*)p)[i] : (long long)((const int*)p)[i];
}

// ---------------------------------------------------------------------------
// Fused kernel: 512 blocks x 512 threads, single resident wave.
// Every warp interleaves, per iteration:
//   - one score step: gather 2 random 512B rows, 4 dot products, reduce
//   - two copy steps: coalesced streaming float4 copy of amem/vmem -> out
// This mixes latency-bound and BW-bound traffic at instruction granularity.
// ---------------------------------------------------------------------------
__global__ __launch_bounds__(512) void fused_kernel(
    const float* __restrict__ audio_emb, const float* __restrict__ video_emb,
    const float* __restrict__ amem, const float* __restrict__ vmem,
    const void* __restrict__ indices, const void* __restrict__ negs,
    float* __restrict__ out_scores,
    float* __restrict__ out_amem, float* __restrict__ out_vmem) {

    const int sid = blockIdx.x;          // 0..511
    const int b = sid >> 1;
    const int n0 = (sid & 1) * 512;
    const int t = threadIdx.x;
    const int lane = t & 31;
    const int w = t >> 5;

    __shared__ float red[17];
    __shared__ __align__(16) float na_s[D];
    __shared__ __align__(16) float nv_s[D];
    __shared__ float sbuf[4][512];

    // normalize this batch row in-block
    float a = 0.f, v = 0.f;
    if (t < D) { a = audio_emb[b * D + t]; v = video_emb[b * D + t]; }
    float sa = block_sum512(a * a, red);
    float sv = block_sum512(v * v, red);
    if (t < D) {
        na_s[t] = a / fmaxf(sqrtf(sa), EPS);
        nv_s[t] = v / fmaxf(sqrtf(sv), EPS);
    }
    __syncthreads();

    const bool is64i = is_i64(indices);
    const bool is64n = is_i64(negs);
    const long long idx = ld_idx(indices, b, is64i);

    const float4 na4 = *(const float4*)(na_s + lane * 4);
    const float4 nv4 = *(const float4*)(nv_s + lane * 4);

    // copy cursors (float4 index space, fits in 32-bit)
    const float4* as = (const float4*)amem;
    const float4* vs = (const float4*)vmem;
    float4* ad = (float4*)out_amem;
    float4* vd = (float4*)out_vmem;
    unsigned int c = (unsigned int)(sid * NWARP + w) * 32u + (unsigned int)lane;

    // 32 score iterations per warp, each fused with 2 copy steps
    for (int i = w; i < 512; i += NWARP) {
        long long neg = ld_idx(negs, (long long)b * NEG + n0 + i, is64n);
        long long row = neg + (neg >= idx ? 1 : 0);
        const float4 av = *(const float4*)(amem + row * D + lane * 4);
        const float4 vv = *(const float4*)(vmem + row * D + lane * 4);

        // streaming copy step (independent of the gathers above)
        if (c < N4) {
            __stcs(ad + c, __ldcs(as + c));
            __stcs(vd + c, __ldcs(vs + c));
        }
        c += CSTRIDE;

        float s_aa = av.x * na4.x + av.y * na4.y + av.z * na4.z + av.w * na4.w;
        float s_av = av.x * nv4.x + av.y * nv4.y + av.z * nv4.z + av.w * nv4.w;
        float s_va = vv.x * na4.x + vv.y * na4.y + vv.z * na4.z + vv.w * na4.w;
        float s_vv = vv.x * nv4.x + vv.y * nv4.y + vv.z * nv4.z + vv.w * nv4.w;

#pragma unroll
        for (int o = 16; o; o >>= 1) {
            s_aa += __shfl_down_sync(0xffffffffu, s_aa, o);
            s_av += __shfl_down_sync(0xffffffffu, s_av, o);
            s_va += __shfl_down_sync(0xffffffffu, s_va, o);
            s_vv += __shfl_down_sync(0xffffffffu, s_vv, o);
        }
        if (lane == 0) {
            // [0]=neg_v·na  [1]=neg_a·nv  [2]=neg_a·na  [3]=neg_v·nv
            sbuf[0][i] = s_va;
            sbuf[1][i] = s_av;
            sbuf[2][i] = s_aa;
            sbuf[3][i] = s_vv;
        }
    }

    // copy tail (32*CSTRIDE = 8.39M < N4 = 9.6M)
    for (; c < N4; c += CSTRIDE) {
        __stcs(ad + c, __ldcs(as + c));
        __stcs(vd + c, __ldcs(vs + c));
    }
    __syncthreads();

    const long long S = (long long)B * (1 + NEG);
    float* dst = out_scores + (long long)b * (1 + NEG) + 1 + n0;
#pragma unroll
    for (int k = 0; k < 4; k++)
        dst[k * S + t] = sbuf[k][t] / TEMPR;
}

// ---------------------------------------------------------------------------
// Finalize: pos scores + momentum scatter. Duplicate indices resolved as
// LAST occurrence wins via a PARALLEL scan (128 threads x <=2 checks each).
// ---------------------------------------------------------------------------
__global__ __launch_bounds__(128) void finalize_kernel(
    const float* __restrict__ audio_emb, const float* __restrict__ video_emb,
    const float* __restrict__ amem, const float* __restrict__ vmem,
    const void* __restrict__ indices,
    float* __restrict__ out_scores,
    float* __restrict__ out_amem, float* __restrict__ out_vmem) {
    __shared__ float sm[4];
    __shared__ int dupflag;
    const int b = blockIdx.x, t = threadIdx.x;
    const bool is64 = is_i64(indices);

    if (t == 0) dupflag = 0;

    float a = audio_emb[b * D + t];
    float v = video_emb[b * D + t];
    float sa = block_sum128(a * a, sm);
    float sv = block_sum128(v * v, sm);
    float na = a / fmaxf(sqrtf(sa), EPS);
    float nv = v / fmaxf(sqrtf(sv), EPS);

    long long idx = ld_idx(indices, b, is64);

    // parallel last-wins duplicate scan
    for (int bb = b + 1 + t; bb < B; bb += 128)
        if (ld_idx(indices, bb, is64) == idx) dupflag = 1;

    float pa = amem[idx * D + t];
    float pv = vmem[idx * D + t];

    float d_apv = block_sum128(na * pv, sm);
    float d_vpa = block_sum128(nv * pa, sm);
    float d_apa = block_sum128(na * pa, sm);
    float d_vpv = block_sum128(nv * pv, sm);
    if (t == 0) {
        const long long S = (long long)B * (1 + NEG);
        out_scores[0 * S + (long long)b * (1 + NEG)] = d_apv / TEMPR;
        out_scores[1 * S + (long long)b * (1 + NEG)] = d_vpa / TEMPR;
        out_scores[2 * S + (long long)b * (1 + NEG)] = d_apa / TEMPR;
        out_scores[3 * S + (long long)b * (1 + NEG)] = d_vpv / TEMPR;
    }

    float ma = pa * 0.5f + na * 0.5f;
    float mv = pv * 0.5f + nv * 0.5f;
    float sma = block_sum128(ma * ma, sm);
    float smv = block_sum128(mv * mv, sm);
    // block_sum128's __syncthreads also makes dupflag visible
    if (!dupflag) {
        out_amem[idx * D + t] = ma / fmaxf(sqrtf(sma), EPS);
        out_vmem[idx * D + t] = mv / fmaxf(sqrtf(smv), EPS);
    }
}

extern "C" void kernel_launch(void* const* d_in, const int* in_sizes, int n_in,
                              void* d_out, int out_size) {
    const float* audio_emb = (const float*)d_in[0];
    const float* video_emb = (const float*)d_in[1];
    const float* amem = (const float*)d_in[2];
    const float* vmem = (const float*)d_in[3];
    const void* indices = d_in[4];
    const void* negs = d_in[5];

    float* out = (float*)d_out;
    float* out_scores = out;                                 // [4,256,1025]
    float* out_amem = out + (size_t)4 * B * (1 + NEG);       // [300000,128]
    float* out_vmem = out_amem + (size_t)SAMPLES * D;        // [300000,128]

    fused_kernel<<<NBLK, 512>>>(audio_emb, video_emb, amem, vmem, indices,
                                negs, out_scores, out_amem, out_vmem);
    finalize_kernel<<<B, 128>>>(audio_emb, video_emb, amem, vmem, indices,
                                out_scores, out_amem, out_vmem);
}

// round 5
// speedup vs baseline: 1.1079x; 1.1079x over previous
#include <cuda_runtime.h>

#define B 256
#define D 128
#define NEG 1024
#define SAMPLES 300000
#define TEMPR 0.07f
#define EPS 1e-12f

__device__ __forceinline__ float warp_sum_xor(float v) {
#pragma unroll
    for (int o = 16; o; o >>= 1) v += __shfl_xor_sync(0xffffffffu, v, o);
    return v;
}

// block-wide sum for 512 threads, broadcast
__device__ __forceinline__ float block_sum512(float v, volatile float* sm) {
    int lane = threadIdx.x & 31, w = threadIdx.x >> 5;
    float s = warp_sum_xor(v);
    if (lane == 0) sm[w] = s;
    __syncthreads();
    float r = 0.f;
    if (threadIdx.x == 0) {
#pragma unroll
        for (int i = 0; i < 16; i++) r += sm[i];
        sm[16] = r;
    }
    __syncthreads();
    r = sm[16];
    __syncthreads();
    return r;
}

// int64 vs int32 detection (JAX x64 demotion hedge)
__device__ __forceinline__ bool is_i64(const void* p) {
    const int* q = (const int*)p;
    return ((q[1] | q[3] | q[5] | q[7]) == 0);
}
__device__ __forceinline__ long long ld_idx(const void* p, long long i, bool is64) {
    return is64 ? ((const long long*)p)[i] : (long long)((const int*)p)[i];
}

__device__ __forceinline__ float dot4(float4 a, float4 b) {
    return a.x * b.x + a.y * b.y + a.z * b.z + a.w * b.w;
}

// ---------------------------------------------------------------------------
// Fused kernel, 1536 blocks x 512 threads, block-level role split:
//   blockIdx%3==1 -> score block (512 total), 2 negatives in flight per warp
//   otherwise     -> copy block (1024 total), streaming float4 copy
// ---------------------------------------------------------------------------
__global__ __launch_bounds__(512) void fused_kernel(
    const float* __restrict__ audio_emb, const float* __restrict__ video_emb,
    const float* __restrict__ amem, const float* __restrict__ vmem,
    const void* __restrict__ indices, const void* __restrict__ negs,
    float* __restrict__ out_scores,
    float* __restrict__ out_amem, float* __restrict__ out_vmem) {

    const int bx = blockIdx.x;
    const int t = threadIdx.x;

    if (bx % 3 == 1) {
        // ------------------------- score block -------------------------
        const int sid = bx / 3;             // 0..511
        const int b = sid >> 1;
        const int n0 = (sid & 1) * 512;
        const int lane = t & 31;
        const int w = t >> 5;

        __shared__ float red[17];
        __shared__ __align__(16) float na_s[D];
        __shared__ __align__(16) float nv_s[D];
        __shared__ float sbuf[4][512];

        float a = 0.f, v = 0.f;
        if (t < D) { a = audio_emb[b * D + t]; v = video_emb[b * D + t]; }
        float sa = block_sum512(a * a, red);
        float sv = block_sum512(v * v, red);
        if (t < D) {
            na_s[t] = a / fmaxf(sqrtf(sa), EPS);
            nv_s[t] = v / fmaxf(sqrtf(sv), EPS);
        }
        __syncthreads();

        const bool is64i = is_i64(indices);
        const bool is64n = is_i64(negs);
        const long long idx = ld_idx(indices, b, is64i);

        const float4 na4 = *(const float4*)(na_s + lane * 4);
        const float4 nv4 = *(const float4*)(nv_s + lane * 4);
        const long long nbase = (long long)b * NEG + n0;

        // each warp handles pairs (i, i+16); 4 independent 512B gathers in flight
#pragma unroll 2
        for (int i = w; i < 512; i += 32) {
            const int j = i + 16;
            long long negA = ld_idx(negs, nbase + i, is64n);
            long long negB = ld_idx(negs, nbase + j, is64n);
            long long rowA = negA + (negA >= idx ? 1 : 0);
            long long rowB = negB + (negB >= idx ? 1 : 0);
            const float4 avA = *(const float4*)(amem + rowA * D + lane * 4);
            const float4 vvA = *(const float4*)(vmem + rowA * D + lane * 4);
            const float4 avB = *(const float4*)(amem + rowB * D + lane * 4);
            const float4 vvB = *(const float4*)(vmem + rowB * D + lane * 4);

            float aaA = dot4(avA, na4), avnA = dot4(avA, nv4);
            float vaA = dot4(vvA, na4), vvnA = dot4(vvA, nv4);
            float aaB = dot4(avB, na4), avnB = dot4(avB, nv4);
            float vaB = dot4(vvB, na4), vvnB = dot4(vvB, nv4);

#pragma unroll
            for (int o = 16; o; o >>= 1) {
                aaA += __shfl_down_sync(0xffffffffu, aaA, o);
                avnA += __shfl_down_sync(0xffffffffu, avnA, o);
                vaA += __shfl_down_sync(0xffffffffu, vaA, o);
                vvnA += __shfl_down_sync(0xffffffffu, vvnA, o);
                aaB += __shfl_down_sync(0xffffffffu, aaB, o);
                avnB += __shfl_down_sync(0xffffffffu, avnB, o);
                vaB += __shfl_down_sync(0xffffffffu, vaB, o);
                vvnB += __shfl_down_sync(0xffffffffu, vvnB, o);
            }
            if (lane == 0) {
                // [0]=neg_v·na  [1]=neg_a·nv  [2]=neg_a·na  [3]=neg_v·nv
                sbuf[0][i] = vaA;  sbuf[0][j] = vaB;
                sbuf[1][i] = avnA; sbuf[1][j] = avnB;
                sbuf[2][i] = aaA;  sbuf[2][j] = aaB;
                sbuf[3][i] = vvnA; sbuf[3][j] = vvnB;
            }
        }
        __syncthreads();

        const long long S = (long long)B * (1 + NEG);
        float* dst = out_scores + (long long)b * (1 + NEG) + 1 + n0;
#pragma unroll
        for (int k = 0; k < 4; k++)
            dst[k * S + t] = sbuf[k][t] / TEMPR;
    } else {
        // ------------------------- copy block --------------------------
        const int cid = (bx / 3) * 2 + (bx % 3 == 0 ? 0 : 1);   // 0..1023
        const size_t N4 = (size_t)SAMPLES * D / 4;
        const size_t stride = (size_t)1024 * 512;
        const float4* as = (const float4*)amem;
        const float4* vs = (const float4*)vmem;
        float4* ad = (float4*)out_amem;
        float4* vd = (float4*)out_vmem;

        size_t i = (size_t)cid * 512 + t;
        for (; i + 3 * stride < N4; i += 4 * stride) {
            float4 x0 = __ldcs(as + i);
            float4 x1 = __ldcs(as + i + stride);
            float4 x2 = __ldcs(as + i + 2 * stride);
            float4 x3 = __ldcs(as + i + 3 * stride);
            __stcs(ad + i, x0);
            __stcs(ad + i + stride, x1);
            __stcs(ad + i + 2 * stride, x2);
            __stcs(ad + i + 3 * stride, x3);
            float4 y0 = __ldcs(vs + i);
            float4 y1 = __ldcs(vs + i + stride);
            float4 y2 = __ldcs(vs + i + 2 * stride);
            float4 y3 = __ldcs(vs + i + 3 * stride);
            __stcs(vd + i, y0);
            __stcs(vd + i + stride, y1);
            __stcs(vd + i + 2 * stride, y2);
            __stcs(vd + i + 3 * stride, y3);
        }
        for (; i < N4; i += stride) {
            __stcs(ad + i, __ldcs(as + i));
            __stcs(vd + i, __ldcs(vs + i));
        }
    }
}

// ---------------------------------------------------------------------------
// Finalize: warp-per-batch-row, all reductions via shfl_xor, no smem barriers.
// Duplicate indices: last occurrence wins (lane-parallel scan + any_sync).
// grid 32 x 256 threads (8 warps -> 8 rows per block).
// ---------------------------------------------------------------------------
__global__ __launch_bounds__(256) void finalize_kernel(
    const float* __restrict__ audio_emb, const float* __restrict__ video_emb,
    const float* __restrict__ amem, const float* __restrict__ vmem,
    const void* __restrict__ indices,
    float* __restrict__ out_scores,
    float* __restrict__ out_amem, float* __restrict__ out_vmem) {
    const int lane = threadIdx.x & 31;
    const int b = blockIdx.x * 8 + (threadIdx.x >> 5);
    const bool is64 = is_i64(indices);

    const float4 a4 = *(const float4*)(audio_emb + b * D + lane * 4);
    const float4 v4 = *(const float4*)(video_emb + b * D + lane * 4);
    float da = fmaxf(sqrtf(warp_sum_xor(dot4(a4, a4))), EPS);
    float dv = fmaxf(sqrtf(warp_sum_xor(dot4(v4, v4))), EPS);
    float4 na4 = make_float4(a4.x / da, a4.y / da, a4.z / da, a4.w / da);
    float4 nv4 = make_float4(v4.x / dv, v4.y / dv, v4.z / dv, v4.w / dv);

    const long long idx = ld_idx(indices, b, is64);
    const float4 pa4 = *(const float4*)(amem + idx * D + lane * 4);
    const float4 pv4 = *(const float4*)(vmem + idx * D + lane * 4);

    float d_apv = warp_sum_xor(dot4(na4, pv4));
    float d_vpa = warp_sum_xor(dot4(nv4, pa4));
    float d_apa = warp_sum_xor(dot4(na4, pa4));
    float d_vpv = warp_sum_xor(dot4(nv4, pv4));
    if (lane == 0) {
        const long long S = (long long)B * (1 + NEG);
        out_scores[0 * S + (long long)b * (1 + NEG)] = d_apv / TEMPR;
        out_scores[1 * S + (long long)b * (1 + NEG)] = d_vpa / TEMPR;
        out_scores[2 * S + (long long)b * (1 + NEG)] = d_apa / TEMPR;
        out_scores[3 * S + (long long)b * (1 + NEG)] = d_vpv / TEMPR;
    }

    // last-occurrence-wins duplicate scan, lane-parallel
    bool dup = false;
    for (int bb = b + 1 + lane; bb < B; bb += 32)
        dup |= (ld_idx(indices, bb, is64) == idx);
    dup = __any_sync(0xffffffffu, dup);

    float4 ma4 = make_float4(pa4.x * 0.5f + na4.x * 0.5f, pa4.y * 0.5f + na4.y * 0.5f,
                             pa4.z * 0.5f + na4.z * 0.5f, pa4.w * 0.5f + na4.w * 0.5f);
    float4 mv4 = make_float4(pv4.x * 0.5f + nv4.x * 0.5f, pv4.y * 0.5f + nv4.y * 0.5f,
                             pv4.z * 0.5f + nv4.z * 0.5f, pv4.w * 0.5f + nv4.w * 0.5f);
    float dma = fmaxf(sqrtf(warp_sum_xor(dot4(ma4, ma4))), EPS);
    float dmv = fmaxf(sqrtf(warp_sum_xor(dot4(mv4, mv4))), EPS);

    if (!dup) {
        *(float4*)(out_amem + idx * D + lane * 4) =
            make_float4(ma4.x / dma, ma4.y / dma, ma4.z / dma, ma4.w / dma);
        *(float4*)(out_vmem + idx * D + lane * 4) =
            make_float4(mv4.x / dmv, mv4.y / dmv, mv4.z / dmv, mv4.w / dmv);
    }
}

extern "C" void kernel_launch(void* const* d_in, const int* in_sizes, int n_in,
                              void* d_out, int out_size) {
    const float* audio_emb = (const float*)d_in[0];
    const float* video_emb = (const float*)d_in[1];
    const float* amem = (const float*)d_in[2];
    const float* vmem = (const float*)d_in[3];
    const void* indices = d_in[4];
    const void* negs = d_in[5];

    float* out = (float*)d_out;
    float* out_scores = out;                                 // [4,256,1025]
    float* out_amem = out + (size_t)4 * B * (1 + NEG);       // [300000,128]
    float* out_vmem = out_amem + (size_t)SAMPLES * D;        // [300000,128]

    fused_kernel<<<1536, 512>>>(audio_emb, video_emb, amem, vmem, indices,
                                negs, out_scores, out_amem, out_vmem);
    finalize_kernel<<<32, 256>>>(audio_emb, video_emb, amem, vmem, indices,
                                 out_scores, out_amem, out_vmem);
}

// round 6
// speedup vs baseline: 1.1613x; 1.0482x over previous
#include <cuda_runtime.h>

#define B 256
#define D 128
#define NEG 1024
#define SAMPLES 300000
#define TEMPR 0.07f
#define EPS 1e-12f

__device__ __forceinline__ float warp_sum_xor(float v) {
#pragma unroll
    for (int o = 16; o; o >>= 1) v += __shfl_xor_sync(0xffffffffu, v, o);
    return v;
}

// block-wide sum for 512 threads, broadcast
__device__ __forceinline__ float block_sum512(float v, volatile float* sm) {
    int lane = threadIdx.x & 31, w = threadIdx.x >> 5;
    float s = warp_sum_xor(v);
    if (lane == 0) sm[w] = s;
    __syncthreads();
    float r = 0.f;
    if (threadIdx.x == 0) {
#pragma unroll
        for (int i = 0; i < 16; i++) r += sm[i];
        sm[16] = r;
    }
    __syncthreads();
    r = sm[16];
    __syncthreads();
    return r;
}

// int64 vs int32 detection (JAX x64 demotion hedge)
__device__ __forceinline__ bool is_i64(const void* p) {
    const int* q = (const int*)p;
    return ((q[1] | q[3] | q[5] | q[7]) == 0);
}
__device__ __forceinline__ long long ld_idx(const void* p, long long i, bool is64) {
    return is64 ? ((const long long*)p)[i] : (long long)((const int*)p)[i];
}

__device__ __forceinline__ float dot4(float4 a, float4 b) {
    return a.x * b.x + a.y * b.y + a.z * b.z + a.w * b.w;
}

// Jointly reduce 4 values across the warp with 11 shuffles (instead of 20).
// Returns: lanes 0-7 hold sum(v0), 8-15 sum(v1), 16-23 sum(v2), 24-31 sum(v3).
__device__ __forceinline__ float reduce4x(float v0, float v1, float v2, float v3,
                                          int lane) {
    v0 += __shfl_xor_sync(0xffffffffu, v0, 16);
    v1 += __shfl_xor_sync(0xffffffffu, v1, 16);
    v2 += __shfl_xor_sync(0xffffffffu, v2, 16);
    v3 += __shfl_xor_sync(0xffffffffu, v3, 16);
    v0 += __shfl_xor_sync(0xffffffffu, v0, 8);
    v1 += __shfl_xor_sync(0xffffffffu, v1, 8);
    v2 += __shfl_xor_sync(0xffffffffu, v2, 8);
    v3 += __shfl_xor_sync(0xffffffffu, v3, 8);
    const int g = (lane >> 3) & 3;
    float x = (g & 2) ? ((g & 1) ? v3 : v2) : ((g & 1) ? v1 : v0);
    x += __shfl_xor_sync(0xffffffffu, x, 4);
    x += __shfl_xor_sync(0xffffffffu, x, 2);
    x += __shfl_xor_sync(0xffffffffu, x, 1);
    return x;
}

// ---------------------------------------------------------------------------
// Score kernel: grid 512 (b = sid/2, half = sid&1), 512 threads, 16 warps.
// Each warp: 32 negatives, 4 per iteration -> 8 independent 512B gathers
// in flight. Scores staged in smem, coalesced write.
// ---------------------------------------------------------------------------
__global__ void __launch_bounds__(512, 2) score_kernel(
    const float* __restrict__ audio_emb, const float* __restrict__ video_emb,
    const float* __restrict__ amem, const float* __restrict__ vmem,
    const void* __restrict__ indices, const void* __restrict__ negs,
    float* __restrict__ out_scores) {

    const int sid = blockIdx.x;
    const int b = sid >> 1;
    const int n0 = (sid & 1) * 512;
    const int t = threadIdx.x;
    const int lane = t & 31;
    const int w = t >> 5;

    __shared__ float red[17];
    __shared__ __align__(16) float na_s[D];
    __shared__ __align__(16) float nv_s[D];
    __shared__ float sbuf[4][512];

    // normalize this batch row in-block
    float a = 0.f, v = 0.f;
    if (t < D) { a = audio_emb[b * D + t]; v = video_emb[b * D + t]; }
    float sa = block_sum512(a * a, red);
    float sv = block_sum512(v * v, red);
    if (t < D) {
        na_s[t] = a / fmaxf(sqrtf(sa), EPS);
        nv_s[t] = v / fmaxf(sqrtf(sv), EPS);
    }
    __syncthreads();

    const bool is64i = is_i64(indices);
    const bool is64n = is_i64(negs);
    const long long idx = ld_idx(indices, b, is64i);

    const float4 na4 = *(const float4*)(na_s + lane * 4);
    const float4 nv4 = *(const float4*)(nv_s + lane * 4);
    const long long nbase = (long long)b * NEG + n0;

    // 8 iterations x 4 negatives per warp
    for (int k = 0; k < 8; k++) {
        const int i0 = w + 64 * k;     // negatives i0, i0+16, i0+32, i0+48
        long long n0i = ld_idx(negs, nbase + i0, is64n);
        long long n1i = ld_idx(negs, nbase + i0 + 16, is64n);
        long long n2i = ld_idx(negs, nbase + i0 + 32, is64n);
        long long n3i = ld_idx(negs, nbase + i0 + 48, is64n);
        long long r0 = n0i + (n0i >= idx ? 1 : 0);
        long long r1 = n1i + (n1i >= idx ? 1 : 0);
        long long r2 = n2i + (n2i >= idx ? 1 : 0);
        long long r3 = n3i + (n3i >= idx ? 1 : 0);

        // 8 independent 512B row gathers
        const float4 a0 = *(const float4*)(amem + r0 * D + lane * 4);
        const float4 v0 = *(const float4*)(vmem + r0 * D + lane * 4);
        const float4 a1 = *(const float4*)(amem + r1 * D + lane * 4);
        const float4 v1 = *(const float4*)(vmem + r1 * D + lane * 4);
        const float4 a2 = *(const float4*)(amem + r2 * D + lane * 4);
        const float4 v2 = *(const float4*)(vmem + r2 * D + lane * 4);
        const float4 a3 = *(const float4*)(amem + r3 * D + lane * 4);
        const float4 v3 = *(const float4*)(vmem + r3 * D + lane * 4);

        // per negative: v_g order = [va, av, aa, vv] matching sbuf slots
        float x0 = reduce4x(dot4(v0, na4), dot4(a0, nv4),
                            dot4(a0, na4), dot4(v0, nv4), lane);
        float x1 = reduce4x(dot4(v1, na4), dot4(a1, nv4),
                            dot4(a1, na4), dot4(v1, nv4), lane);
        float x2 = reduce4x(dot4(v2, na4), dot4(a2, nv4),
                            dot4(a2, na4), dot4(v2, nv4), lane);
        float x3 = reduce4x(dot4(v3, na4), dot4(a3, nv4),
                            dot4(a3, na4), dot4(v3, nv4), lane);

        if ((lane & 7) == 0) {
            const int slot = lane >> 3;
            sbuf[slot][i0] = x0;
            sbuf[slot][i0 + 16] = x1;
            sbuf[slot][i0 + 32] = x2;
            sbuf[slot][i0 + 48] = x3;
        }
    }
    __syncthreads();

    const long long S = (long long)B * (1 + NEG);
    float* dst = out_scores + (long long)b * (1 + NEG) + 1 + n0;
#pragma unroll
    for (int k = 0; k < 4; k++)
        dst[k * S + t] = sbuf[k][t] / TEMPR;
}

// ---------------------------------------------------------------------------
// Finalize: warp-per-batch-row (grid 256 x 32). Pos scores + momentum scatter
// with last-occurrence-wins duplicate resolution.
// ---------------------------------------------------------------------------
__global__ __launch_bounds__(32) void finalize_kernel(
    const float* __restrict__ audio_emb, const float* __restrict__ video_emb,
    const float* __restrict__ amem, const float* __restrict__ vmem,
    const void* __restrict__ indices,
    float* __restrict__ out_scores,
    float* __restrict__ out_amem, float* __restrict__ out_vmem) {
    const int lane = threadIdx.x;
    const int b = blockIdx.x;
    const bool is64 = is_i64(indices);

    const float4 a4 = *(const float4*)(audio_emb + b * D + lane * 4);
    const float4 v4 = *(const float4*)(video_emb + b * D + lane * 4);
    float da = fmaxf(sqrtf(warp_sum_xor(dot4(a4, a4))), EPS);
    float dv = fmaxf(sqrtf(warp_sum_xor(dot4(v4, v4))), EPS);
    float4 na4 = make_float4(a4.x / da, a4.y / da, a4.z / da, a4.w / da);
    float4 nv4 = make_float4(v4.x / dv, v4.y / dv, v4.z / dv, v4.w / dv);

    const long long idx = ld_idx(indices, b, is64);
    const float4 pa4 = *(const float4*)(amem + idx * D + lane * 4);
    const float4 pv4 = *(const float4*)(vmem + idx * D + lane * 4);

    float d_apv = warp_sum_xor(dot4(na4, pv4));
    float d_vpa = warp_sum_xor(dot4(nv4, pa4));
    float d_apa = warp_sum_xor(dot4(na4, pa4));
    float d_vpv = warp_sum_xor(dot4(nv4, pv4));
    if (lane == 0) {
        const long long S = (long long)B * (1 + NEG);
        out_scores[0 * S + (long long)b * (1 + NEG)] = d_apv / TEMPR;
        out_scores[1 * S + (long long)b * (1 + NEG)] = d_vpa / TEMPR;
        out_scores[2 * S + (long long)b * (1 + NEG)] = d_apa / TEMPR;
        out_scores[3 * S + (long long)b * (1 + NEG)] = d_vpv / TEMPR;
    }

    // last-occurrence-wins duplicate scan, lane-parallel
    bool dup = false;
    for (int bb = b + 1 + lane; bb < B; bb += 32)
        dup |= (ld_idx(indices, bb, is64) == idx);
    dup = __any_sync(0xffffffffu, dup);

    float4 ma4 = make_float4(pa4.x * 0.5f + na4.x * 0.5f, pa4.y * 0.5f + na4.y * 0.5f,
                             pa4.z * 0.5f + na4.z * 0.5f, pa4.w * 0.5f + na4.w * 0.5f);
    float4 mv4 = make_float4(pv4.x * 0.5f + nv4.x * 0.5f, pv4.y * 0.5f + nv4.y * 0.5f,
                             pv4.z * 0.5f + nv4.z * 0.5f, pv4.w * 0.5f + nv4.w * 0.5f);
    float dma = fmaxf(sqrtf(warp_sum_xor(dot4(ma4, ma4))), EPS);
    float dmv = fmaxf(sqrtf(warp_sum_xor(dot4(mv4, mv4))), EPS);

    if (!dup) {
        *(float4*)(out_amem + idx * D + lane * 4) =
            make_float4(ma4.x / dma, ma4.y / dma, ma4.z / dma, ma4.w / dma);
        *(float4*)(out_vmem + idx * D + lane * 4) =
            make_float4(mv4.x / dmv, mv4.y / dmv, mv4.z / dmv, mv4.w / dmv);
    }
}

extern "C" void kernel_launch(void* const* d_in, const int* in_sizes, int n_in,
                              void* d_out, int out_size) {
    const float* audio_emb = (const float*)d_in[0];
    const float* video_emb = (const float*)d_in[1];
    const float* amem = (const float*)d_in[2];
    const float* vmem = (const float*)d_in[3];
    const void* indices = d_in[4];
    const void* negs = d_in[5];

    float* out = (float*)d_out;
    float* out_scores = out;                                 // [4,256,1025]
    float* out_amem = out + (size_t)4 * B * (1 + NEG);       // [300000,128]
    float* out_vmem = out_amem + (size_t)SAMPLES * D;        // [300000,128]

    // serial skeleton: mixing gather+stream traffic measured SLOWER (R3-R5)
    cudaMemcpyAsync(out_amem, amem, (size_t)SAMPLES * D * sizeof(float),
                    cudaMemcpyDeviceToDevice, 0);
    cudaMemcpyAsync(out_vmem, vmem, (size_t)SAMPLES * D * sizeof(float),
                    cudaMemcpyDeviceToDevice, 0);

    score_kernel<<<512, 512>>>(audio_emb, video_emb, amem, vmem, indices,
                               negs, out_scores);
    finalize_kernel<<<B, 32>>>(audio_emb, video_emb, amem, vmem, indices,
                               out_scores, out_amem, out_vmem);
}

// round 7
// speedup vs baseline: 1.2017x; 1.0348x over previous
#include <cuda_runtime.h>

#define B 256
#define D 128
#define NEG 1024
#define SAMPLES 300000
#define TEMPR 0.07f
#define EPS 1e-12f

__device__ __forceinline__ float warp_sum(float v) {
#pragma unroll
    for (int o = 16; o; o >>= 1) v += __shfl_down_sync(0xffffffffu, v, o);
    return v;
}

// block-wide sum for 512 threads (16 warps), broadcast
__device__ __forceinline__ float block_sum512(float v, volatile float* sm) {
    int lane = threadIdx.x & 31, w = threadIdx.x >> 5;
    float s = warp_sum(v);
    if (lane == 0) sm[w] = s;
    __syncthreads();
    float r = 0.f;
    if (threadIdx.x == 0) {
#pragma unroll
        for (int i = 0; i < 16; i++) r += sm[i];
        sm[16] = r;
    }
    __syncthreads();
    r = sm[16];
    __syncthreads();
    return r;
}

// block-wide sum for 128 threads (4 warps), broadcast
__device__ __forceinline__ float block_sum128(float v, volatile float* sm) {
    int lane = threadIdx.x & 31, w = threadIdx.x >> 5;
    float s = warp_sum(v);
    if (lane == 0) sm[w] = s;
    __syncthreads();
    float r = sm[0] + sm[1] + sm[2] + sm[3];
    __syncthreads();
    return r;
}

// int64 vs int32 detection (JAX x64 demotion hedge)
__device__ __forceinline__ bool is_i64(const void* p) {
    const int* q = (const int*)p;
    return ((q[1] | q[3] | q[5] | q[7]) == 0);
}
__device__ __forceinline__ long long ld_idx(const void* p, long long i, bool is64) {
    return is64 ? ((const long long*)p)[i] : (long long)((const int*)p)[i];
}

// ---------------------------------------------------------------------------
// Fused kernel (R3 configuration — best measured copy+score engine, 132.5us):
// 1536 blocks x 512 threads.
//   blockIdx%3==1 -> score block (512 total: b = sid/2, half = sid&1),
//                    ONE negative per warp-iteration (gentle gathers mix
//                    best with the streaming copy traffic — R5 measured
//                    deeper MLP regressing 132.5 -> 143.5)
//   otherwise     -> copy block (1024 total), streaming float4 copy
// ---------------------------------------------------------------------------
__global__ __launch_bounds__(512) void fused_kernel(
    const float* __restrict__ audio_emb, const float* __restrict__ video_emb,
    const float* __restrict__ amem, const float* __restrict__ vmem,
    const void* __restrict__ indices, const void* __restrict__ negs,
    float* __restrict__ out_scores,
    float* __restrict__ out_amem, float* __restrict__ out_vmem) {

    const int bx = blockIdx.x;
    const int t = threadIdx.x;

    if (bx % 3 == 1) {
        // ------------------------- score block -------------------------
        const int sid = bx / 3;             // 0..511
        const int b = sid >> 1;
        const int n0 = (sid & 1) * 512;
        const int lane = t & 31;
        const int w = t >> 5;

        __shared__ float red[17];
        __shared__ __align__(16) float na_s[D];
        __shared__ __align__(16) float nv_s[D];
        __shared__ float sbuf[4][512];

        float a = 0.f, v = 0.f;
        if (t < D) { a = audio_emb[b * D + t]; v = video_emb[b * D + t]; }
        float sa = block_sum512(a * a, red);
        float sv = block_sum512(v * v, red);
        if (t < D) {
            na_s[t] = a / fmaxf(sqrtf(sa), EPS);
            nv_s[t] = v / fmaxf(sqrtf(sv), EPS);
        }
        __syncthreads();

        const bool is64i = is_i64(indices);
        const bool is64n = is_i64(negs);
        const long long idx = ld_idx(indices, b, is64i);

        const float4 na4 = *(const float4*)(na_s + lane * 4);
        const float4 nv4 = *(const float4*)(nv_s + lane * 4);

#pragma unroll 2
        for (int i = w; i < 512; i += 16) {
            long long neg = ld_idx(negs, (long long)b * NEG + n0 + i, is64n);
            long long row = neg + (neg >= idx ? 1 : 0);
            const float4 av = *(const float4*)(amem + row * D + lane * 4);
            const float4 vv = *(const float4*)(vmem + row * D + lane * 4);

            float s_aa = av.x * na4.x + av.y * na4.y + av.z * na4.z + av.w * na4.w;
            float s_av = av.x * nv4.x + av.y * nv4.y + av.z * nv4.z + av.w * nv4.w;
            float s_va = vv.x * na4.x + vv.y * na4.y + vv.z * na4.z + vv.w * na4.w;
            float s_vv = vv.x * nv4.x + vv.y * nv4.y + vv.z * nv4.z + vv.w * nv4.w;

#pragma unroll
            for (int o = 16; o; o >>= 1) {
                s_aa += __shfl_down_sync(0xffffffffu, s_aa, o);
                s_av += __shfl_down_sync(0xffffffffu, s_av, o);
                s_va += __shfl_down_sync(0xffffffffu, s_va, o);
                s_vv += __shfl_down_sync(0xffffffffu, s_vv, o);
            }
            if (lane == 0) {
                // [0]=neg_v·na  [1]=neg_a·nv  [2]=neg_a·na  [3]=neg_v·nv
                sbuf[0][i] = s_va;
                sbuf[1][i] = s_av;
                sbuf[2][i] = s_aa;
                sbuf[3][i] = s_vv;
            }
        }
        __syncthreads();

        const long long S = (long long)B * (1 + NEG);
        float* dst = out_scores + (long long)b * (1 + NEG) + 1 + n0;
#pragma unroll
        for (int k = 0; k < 4; k++)
            dst[k * S + t] = sbuf[k][t] / TEMPR;
    } else {
        // ------------------------- copy block --------------------------
        const int cid = (bx / 3) * 2 + (bx % 3 == 0 ? 0 : 1);   // 0..1023
        const size_t N4 = (size_t)SAMPLES * D / 4;
        const size_t stride = (size_t)1024 * 512;
        const float4* as = (const float4*)amem;
        const float4* vs = (const float4*)vmem;
        float4* ad = (float4*)out_amem;
        float4* vd = (float4*)out_vmem;

        size_t i = (size_t)cid * 512 + t;
        for (; i + 3 * stride < N4; i += 4 * stride) {
            float4 x0 = __ldcs(as + i);
            float4 x1 = __ldcs(as + i + stride);
            float4 x2 = __ldcs(as + i + 2 * stride);
            float4 x3 = __ldcs(as + i + 3 * stride);
            __stcs(ad + i, x0);
            __stcs(ad + i + stride, x1);
            __stcs(ad + i + 2 * stride, x2);
            __stcs(ad + i + 3 * stride, x3);
            float4 y0 = __ldcs(vs + i);
            float4 y1 = __ldcs(vs + i + stride);
            float4 y2 = __ldcs(vs + i + 2 * stride);
            float4 y3 = __ldcs(vs + i + 3 * stride);
            __stcs(vd + i, y0);
            __stcs(vd + i + stride, y1);
            __stcs(vd + i + 2 * stride, y2);
            __stcs(vd + i + 3 * stride, y3);
        }
        for (; i < N4; i += stride) {
            __stcs(ad + i, __ldcs(as + i));
            __stcs(vd + i, __ldcs(vs + i));
        }
    }
}

// ---------------------------------------------------------------------------
// Finalize (R1's fast 128-thread block-per-row structure, ~4.3us measured,
// plus the parallel dup scan): pos scores + momentum scatter, last wins.
// ---------------------------------------------------------------------------
__global__ __launch_bounds__(128) void finalize_kernel(
    const float* __restrict__ audio_emb, const float* __restrict__ video_emb,
    const float* __restrict__ amem, const float* __restrict__ vmem,
    const void* __restrict__ indices,
    float* __restrict__ out_scores,
    float* __restrict__ out_amem, float* __restrict__ out_vmem) {
    __shared__ float sm[4];
    __shared__ int dupflag;
    const int b = blockIdx.x, t = threadIdx.x;
    const bool is64 = is_i64(indices);

    if (t == 0) dupflag = 0;

    float a = audio_emb[b * D + t];
    float v = video_emb[b * D + t];
    float sa = block_sum128(a * a, sm);
    float sv = block_sum128(v * v, sm);
    float na = a / fmaxf(sqrtf(sa), EPS);
    float nv = v / fmaxf(sqrtf(sv), EPS);

    long long idx = ld_idx(indices, b, is64);

    // parallel last-wins duplicate scan (<=2 checks per thread)
    for (int bb = b + 1 + t; bb < B; bb += 128)
        if (ld_idx(indices, bb, is64) == idx) dupflag = 1;

    float pa = amem[idx * D + t];
    float pv = vmem[idx * D + t];

    float d_apv = block_sum128(na * pv, sm);
    float d_vpa = block_sum128(nv * pa, sm);
    float d_apa = block_sum128(na * pa, sm);
    float d_vpv = block_sum128(nv * pv, sm);
    if (t == 0) {
        const long long S = (long long)B * (1 + NEG);
        out_scores[0 * S + (long long)b * (1 + NEG)] = d_apv / TEMPR;
        out_scores[1 * S + (long long)b * (1 + NEG)] = d_vpa / TEMPR;
        out_scores[2 * S + (long long)b * (1 + NEG)] = d_apa / TEMPR;
        out_scores[3 * S + (long long)b * (1 + NEG)] = d_vpv / TEMPR;
    }

    float ma = pa * 0.5f + na * 0.5f;
    float mv = pv * 0.5f + nv * 0.5f;
    float sma = block_sum128(ma * ma, sm);
    float smv = block_sum128(mv * mv, sm);
    // block_sum128's barriers make dupflag visible to all threads
    if (!dupflag) {
        out_amem[idx * D + t] = ma / fmaxf(sqrtf(sma), EPS);
        out_vmem[idx * D + t] = mv / fmaxf(sqrtf(smv), EPS);
    }
}

extern "C" void kernel_launch(void* const* d_in, const int* in_sizes, int n_in,
                              void* d_out, int out_size) {
    const float* audio_emb = (const float*)d_in[0];
    const float* video_emb = (const float*)d_in[1];
    const float* amem = (const float*)d_in[2];
    const float* vmem = (const float*)d_in[3];
    const void* indices = d_in[4];
    const void* negs = d_in[5];

    float* out = (float*)d_out;
    float* out_scores = out;                                 // [4,256,1025]
    float* out_amem = out + (size_t)4 * B * (1 + NEG);       // [300000,128]
    float* out_vmem = out_amem + (size_t)SAMPLES * D;        // [300000,128]

    fused_kernel<<<1536, 512>>>(audio_emb, video_emb, amem, vmem, indices,
                                negs, out_scores, out_amem, out_vmem);
    finalize_kernel<<<B, 128>>>(audio_emb, video_emb, amem, vmem, indices,
                                out_scores, out_amem, out_vmem);
}

// round 8
// speedup vs baseline: 1.2412x; 1.0329x over previous
#include <cuda_runtime.h>

#define B 256
#define D 128
#define NEG 1024
#define SAMPLES 300000
#define TEMPR 0.07f
#define EPS 1e-12f

__device__ __forceinline__ float warp_sum(float v) {
#pragma unroll
    for (int o = 16; o; o >>= 1) v += __shfl_down_sync(0xffffffffu, v, o);
    return v;
}

// block-wide sum for 512 threads (16 warps), broadcast
__device__ __forceinline__ float block_sum512(float v, volatile float* sm) {
    int lane = threadIdx.x & 31, w = threadIdx.x >> 5;
    float s = warp_sum(v);
    if (lane == 0) sm[w] = s;
    __syncthreads();
    float r = 0.f;
    if (threadIdx.x == 0) {
#pragma unroll
        for (int i = 0; i < 16; i++) r += sm[i];
        sm[16] = r;
    }
    __syncthreads();
    r = sm[16];
    __syncthreads();
    return r;
}

// block-wide sum for 128 threads (4 warps), broadcast
__device__ __forceinline__ float block_sum128(float v, volatile float* sm) {
    int lane = threadIdx.x & 31, w = threadIdx.x >> 5;
    float s = warp_sum(v);
    if (lane == 0) sm[w] = s;
    __syncthreads();
    float r = sm[0] + sm[1] + sm[2] + sm[3];
    __syncthreads();
    return r;
}

// int64 vs int32 detection (JAX x64 demotion hedge)
__device__ __forceinline__ bool is_i64(const void* p) {
    const int* q = (const int*)p;
    return ((q[1] | q[3] | q[5] | q[7]) == 0);
}
__device__ __forceinline__ long long ld_idx(const void* p, long long i, bool is64) {
    return is64 ? ((const long long*)p)[i] : (long long)((const int*)p)[i];
}

// ---------------------------------------------------------------------------
// Fused kernel, grid 2048 x 512, 1:1 role split (score side was the binding
// constraint at 2:1 — it is concurrency-limited, copy is BW-limited):
//   odd  bx -> score block (1024 total: b = sid/4, quarter = sid%4, 256 negs)
//   even bx -> copy block  (1024 total), streaming float4 copy
// ---------------------------------------------------------------------------
__global__ __launch_bounds__(512) void fused_kernel(
    const float* __restrict__ audio_emb, const float* __restrict__ video_emb,
    const float* __restrict__ amem, const float* __restrict__ vmem,
    const void* __restrict__ indices, const void* __restrict__ negs,
    float* __restrict__ out_scores,
    float* __restrict__ out_amem, float* __restrict__ out_vmem) {

    const int bx = blockIdx.x;
    const int t = threadIdx.x;

    if (bx & 1) {
        // ------------------------- score block -------------------------
        const int sid = bx >> 1;            // 0..1023
        const int b = sid >> 2;
        const int n0 = (sid & 3) * 256;
        const int lane = t & 31;
        const int w = t >> 5;

        __shared__ float red[17];
        __shared__ __align__(16) float na_s[D];
        __shared__ __align__(16) float nv_s[D];
        __shared__ float sbuf[4][256];

        float a = 0.f, v = 0.f;
        if (t < D) { a = audio_emb[b * D + t]; v = video_emb[b * D + t]; }
        float sa = block_sum512(a * a, red);
        float sv = block_sum512(v * v, red);
        if (t < D) {
            na_s[t] = a / fmaxf(sqrtf(sa), EPS);
            nv_s[t] = v / fmaxf(sqrtf(sv), EPS);
        }
        __syncthreads();

        const bool is64i = is_i64(indices);
        const bool is64n = is_i64(negs);
        const long long idx = ld_idx(indices, b, is64i);

        const float4 na4 = *(const float4*)(na_s + lane * 4);
        const float4 nv4 = *(const float4*)(nv_s + lane * 4);

#pragma unroll 2
        for (int i = w; i < 256; i += 16) {
            long long neg = ld_idx(negs, (long long)b * NEG + n0 + i, is64n);
            long long row = neg + (neg >= idx ? 1 : 0);
            const float4 av = *(const float4*)(amem + row * D + lane * 4);
            const float4 vv = *(const float4*)(vmem + row * D + lane * 4);

            float s_aa = av.x * na4.x + av.y * na4.y + av.z * na4.z + av.w * na4.w;
            float s_av = av.x * nv4.x + av.y * nv4.y + av.z * nv4.z + av.w * nv4.w;
            float s_va = vv.x * na4.x + vv.y * na4.y + vv.z * na4.z + vv.w * na4.w;
            float s_vv = vv.x * nv4.x + vv.y * nv4.y + vv.z * nv4.z + vv.w * nv4.w;

#pragma unroll
            for (int o = 16; o; o >>= 1) {
                s_aa += __shfl_down_sync(0xffffffffu, s_aa, o);
                s_av += __shfl_down_sync(0xffffffffu, s_av, o);
                s_va += __shfl_down_sync(0xffffffffu, s_va, o);
                s_vv += __shfl_down_sync(0xffffffffu, s_vv, o);
            }
            if (lane == 0) {
                // [0]=neg_v·na  [1]=neg_a·nv  [2]=neg_a·na  [3]=neg_v·nv
                sbuf[0][i] = s_va;
                sbuf[1][i] = s_av;
                sbuf[2][i] = s_aa;
                sbuf[3][i] = s_vv;
            }
        }
        __syncthreads();

        const long long S = (long long)B * (1 + NEG);
        float* dst = out_scores + (long long)b * (1 + NEG) + 1 + n0;
        if (t < 256) {
#pragma unroll
            for (int k = 0; k < 4; k++)
                dst[k * S + t] = sbuf[k][t] / TEMPR;
        }
    } else {
        // ------------------------- copy block --------------------------
        const int cid = bx >> 1;            // 0..1023 (same layout as R7)
        const size_t N4 = (size_t)SAMPLES * D / 4;
        const size_t stride = (size_t)1024 * 512;
        const float4* as = (const float4*)amem;
        const float4* vs = (const float4*)vmem;
        float4* ad = (float4*)out_amem;
        float4* vd = (float4*)out_vmem;

        size_t i = (size_t)cid * 512 + t;
        for (; i + 3 * stride < N4; i += 4 * stride) {
            float4 x0 = __ldcs(as + i);
            float4 x1 = __ldcs(as + i + stride);
            float4 x2 = __ldcs(as + i + 2 * stride);
            float4 x3 = __ldcs(as + i + 3 * stride);
            __stcs(ad + i, x0);
            __stcs(ad + i + stride, x1);
            __stcs(ad + i + 2 * stride, x2);
            __stcs(ad + i + 3 * stride, x3);
            float4 y0 = __ldcs(vs + i);
            float4 y1 = __ldcs(vs + i + stride);
            float4 y2 = __ldcs(vs + i + 2 * stride);
            float4 y3 = __ldcs(vs + i + 3 * stride);
            __stcs(vd + i, y0);
            __stcs(vd + i + stride, y1);
            __stcs(vd + i + 2 * stride, y2);
            __stcs(vd + i + 3 * stride, y3);
        }
        for (; i < N4; i += stride) {
            __stcs(ad + i, __ldcs(as + i));
            __stcs(vd + i, __ldcs(vs + i));
        }
    }
}

// ---------------------------------------------------------------------------
// Finalize (unchanged from R7): pos scores + momentum scatter, last wins.
// ---------------------------------------------------------------------------
__global__ __launch_bounds__(128) void finalize_kernel(
    const float* __restrict__ audio_emb, const float* __restrict__ video_emb,
    const float* __restrict__ amem, const float* __restrict__ vmem,
    const void* __restrict__ indices,
    float* __restrict__ out_scores,
    float* __restrict__ out_amem, float* __restrict__ out_vmem) {
    __shared__ float sm[4];
    __shared__ int dupflag;
    const int b = blockIdx.x, t = threadIdx.x;
    const bool is64 = is_i64(indices);

    if (t == 0) dupflag = 0;

    float a = audio_emb[b * D + t];
    float v = video_emb[b * D + t];
    float sa = block_sum128(a * a, sm);
    float sv = block_sum128(v * v, sm);
    float na = a / fmaxf(sqrtf(sa), EPS);
    float nv = v / fmaxf(sqrtf(sv), EPS);

    long long idx = ld_idx(indices, b, is64);

    // parallel last-wins duplicate scan (<=2 checks per thread)
    for (int bb = b + 1 + t; bb < B; bb += 128)
        if (ld_idx(indices, bb, is64) == idx) dupflag = 1;

    float pa = amem[idx * D + t];
    float pv = vmem[idx * D + t];

    float d_apv = block_sum128(na * pv, sm);
    float d_vpa = block_sum128(nv * pa, sm);
    float d_apa = block_sum128(na * pa, sm);
    float d_vpv = block_sum128(nv * pv, sm);
    if (t == 0) {
        const long long S = (long long)B * (1 + NEG);
        out_scores[0 * S + (long long)b * (1 + NEG)] = d_apv / TEMPR;
        out_scores[1 * S + (long long)b * (1 + NEG)] = d_vpa / TEMPR;
        out_scores[2 * S + (long long)b * (1 + NEG)] = d_apa / TEMPR;
        out_scores[3 * S + (long long)b * (1 + NEG)] = d_vpv / TEMPR;
    }

    float ma = pa * 0.5f + na * 0.5f;
    float mv = pv * 0.5f + nv * 0.5f;
    float sma = block_sum128(ma * ma, sm);
    float smv = block_sum128(mv * mv, sm);
    // block_sum128's barriers make dupflag visible to all threads
    if (!dupflag) {
        out_amem[idx * D + t] = ma / fmaxf(sqrtf(sma), EPS);
        out_vmem[idx * D + t] = mv / fmaxf(sqrtf(smv), EPS);
    }
}

extern "C" void kernel_launch(void* const* d_in, const int* in_sizes, int n_in,
                              void* d_out, int out_size) {
    const float* audio_emb = (const float*)d_in[0];
    const float* video_emb = (const float*)d_in[1];
    const float* amem = (const float*)d_in[2];
    const float* vmem = (const float*)d_in[3];
    const void* indices = d_in[4];
    const void* negs = d_in[5];

    float* out = (float*)d_out;
    float* out_scores = out;                                 // [4,256,1025]
    float* out_amem = out + (size_t)4 * B * (1 + NEG);       // [300000,128]
    float* out_vmem = out_amem + (size_t)SAMPLES * D;        // [300000,128]

    fused_kernel<<<2048, 512>>>(audio_emb, video_emb, amem, vmem, indices,
                                negs, out_scores, out_amem, out_vmem);
    finalize_kernel<<<B, 128>>>(audio_emb, video_emb, amem, vmem, indices,
                                out_scores, out_amem, out_vmem);
}